// round 15
// baseline (speedup 1.0000x reference)
#include <cuda_runtime.h>
#include <cuda_fp16.h>

#define GRID_SZ 256
#define BRICKS 128              // A-volume bricks per axis (2x2x2 cells)
#define BX_B   132             // B-volume x-brick stride (129 used, padded)
#define NVOX (GRID_SZ * GRID_SZ * GRID_SZ)

// Dual-grid fp16 difference volumes, 2x2x2-brick layout, 16 B per brick:
//   cell = (z&1)*4 + (y&1)*2 + (x&1)
// A: x-bricks aligned even: brick bx covers x in {2bx, 2bx+1},   bx in [0,127]
// B: x-bricks aligned odd:  brick j  covers x in {2j-1, 2j},     j  in [0,128]
// A splat with even x0 lands wholly in one A x-brick; odd x0 in one B x-brick
// -> exactly one RED per (y,z) brick combo: E[REDs/splat] = 1*1.5*1.5 = 2.25.
// Voxel value = A(x,y,z) + B(x,y,z); the reduce gathers both before Huber.
// Zero-initialized at load; the reduce re-zeros everything it reads.
__device__ __align__(16) __half g_A[(size_t)BRICKS * BRICKS * BRICKS * 8];
__device__ __align__(16) __half g_B[(size_t)BRICKS * BRICKS * BX_B * 8];

__device__ __forceinline__ void red_add_v4_h2(__half* addr, unsigned h0,
                                              unsigned h1, unsigned h2_,
                                              unsigned h3) {
    asm volatile("red.global.add.noftz.v4.f16x2 [%0], {%1,%2,%3,%4};"
                 :: "l"(addr), "r"(h0), "r"(h1), "r"(h2_), "r"(h3)
                 : "memory");
}

// y/z axes keep the 2-brick decomposition (shared alignment in A and B).
struct Axis {
    int n;
    int b[2];
    float w0[2], w1[2];
};

__device__ __forceinline__ Axis axis_decomp(int c0, float wlo, float whi) {
    Axis a;
    a.n = 0;
    int bA = c0 >> 1;  // arithmetic shift: c0=-1 -> -1 (rejected below)
    if (!(c0 & 1)) {
        if ((unsigned)bA < BRICKS) {
            a.b[0] = bA; a.w0[0] = wlo; a.w1[0] = whi; a.n = 1;
        }
    } else {
        if ((unsigned)bA < BRICKS) {
            a.b[a.n] = bA; a.w0[a.n] = 0.0f; a.w1[a.n] = wlo; a.n++;
        }
        int bB = bA + 1;
        if ((unsigned)bB < BRICKS) {
            a.b[a.n] = bB; a.w0[a.n] = whi; a.w1[a.n] = 0.0f; a.n++;
        }
    }
    return a;
}

__device__ __forceinline__ void splat(float px, float py, float pz, float s) {
    // Match reference arithmetic exactly: p = ((g+1)*size - 1) * 0.5
    float x = ((px + 1.0f) * 256.0f - 1.0f) * 0.5f;
    float y = ((py + 1.0f) * 256.0f - 1.0f) * 0.5f;
    float z = ((pz + 1.0f) * 256.0f - 1.0f) * 0.5f;
    float x0f = floorf(x), y0f = floorf(y), z0f = floorf(z);
    int x0 = (int)x0f, y0 = (int)y0f, z0 = (int)z0f;
    float fx = x - x0f, fy = y - y0f, fz = z - z0f;
    float wx0 = 1.0f - fx, wx1 = fx;

    // x-axis: single brick in A (x0 even) or B (x0 odd). Lane order (w0,w1)
    // is identical in both layouts.
    int par = x0 & 1;                 // works for negative x0 too
    int bx = (x0 >> 1) + par;         // even: x0>>1 ; odd: (x0+1)>>1
    __half* vol;
    int xstride;
    if (par) {
        if ((unsigned)bx > 128u) return;     // j in [0,128]
        if (x0 < 0) wx0 = 0.0f;              // lane x=-1 (exists, never read)
        if (x0 >= GRID_SZ - 1) wx1 = 0.0f;   // lane x=256
        vol = g_B; xstride = BX_B;
    } else {
        if ((unsigned)x0 >= (unsigned)(GRID_SZ - 1)) return; // x0 in [0,254]
        vol = g_A; xstride = BRICKS;
    }

    Axis ay = axis_decomp(y0, 1.0f - fy, fy);
    Axis az = axis_decomp(z0, (1.0f - fz) * s, fz * s);  // fold sign into z

#pragma unroll
    for (int i = 0; i < 2; i++) {
        if (i >= az.n) break;
        float t0 = az.w0[i], t1 = az.w1[i];
        int zb = az.b[i] * BRICKS;
#pragma unroll
        for (int j = 0; j < 2; j++) {
            if (j >= ay.n) break;
            float a00 = t0 * ay.w0[j];  // z0,y0
            float a01 = t0 * ay.w1[j];  // z0,y1
            float a10 = t1 * ay.w0[j];  // z1,y0
            float a11 = t1 * ay.w1[j];  // z1,y1
            __half* p = vol + ((size_t)(zb + ay.b[j]) * xstride + bx) * 8;
            __half2 q0 = __floats2half2_rn(a00 * wx0, a00 * wx1); // z0y0
            __half2 q1 = __floats2half2_rn(a01 * wx0, a01 * wx1); // z0y1
            __half2 q2 = __floats2half2_rn(a10 * wx0, a10 * wx1); // z1y0
            __half2 q3 = __floats2half2_rn(a11 * wx0, a11 * wx1); // z1y1
            red_add_v4_h2(p,
                          *(unsigned*)&q0, *(unsigned*)&q1,
                          *(unsigned*)&q2, *(unsigned*)&q3);
        }
    }
}

__global__ void scatter_kernel(const float* __restrict__ pred,
                               const float* __restrict__ gt,
                               const float* __restrict__ coords,
                               float* __restrict__ out, int n) {
    int i = blockIdx.x * blockDim.x + threadIdx.x;
    if (i == 0) out[0] = 0.0f;  // reduce kernel runs after us in stream order
    if (i >= n) return;

    // Streaming (evict-first) loads: keep L2 capacity for the volumes.
    float cx = __ldcs(&coords[3 * i + 0]);
    float cy = __ldcs(&coords[3 * i + 1]);
    float cz = __ldcs(&coords[3 * i + 2]);
    float p0 = __ldcs(&pred[3 * i + 0]);
    float p1 = __ldcs(&pred[3 * i + 1]);
    float p2 = __ldcs(&pred[3 * i + 2]);
    float g0 = __ldcs(&gt[3 * i + 0]);
    float g1 = __ldcs(&gt[3 * i + 1]);
    float g2 = __ldcs(&gt[3 * i + 2]);

    splat(cx + p0, cy + p1, cz + p2,  1.0f);
    splat(cx + g0, cy + g1, cz + g2, -1.0f);
}

__device__ __forceinline__ float huber(float d) {
    float ad = fabsf(d);
    return (ad <= 1.0f) ? 0.5f * d * d : (ad - 0.5f);
}

// A h2 pair (voxels x=2k, 2k+1) combines with B[k] high lane (x=2k) and
// B[k+1] low lane (x=2k+1).
__device__ __forceinline__ float pair_huber(unsigned ua, unsigned ub0,
                                            unsigned ub1) {
    float2 fa = __half22float2(*(__half2*)&ua);
    float2 f0 = __half22float2(*(__half2*)&ub0);
    float2 f1 = __half22float2(*(__half2*)&ub1);
    return huber(fa.x + f0.y) + huber(fa.y + f1.x);
}

// 1024 blocks x 256 threads = 262144 threads; each owns 8 consecutive
// A x-bricks (16 voxels in x) of one (zb,yb) row + the 9 overlapping
// B x-bricks. Loads 8+9 uint4, re-zeros what it read, Hubers 64 voxels.
#define RED_BLOCKS 1024
#define RED_THREADS 256

__global__ void __launch_bounds__(RED_THREADS, 2)
huber_reduce_kernel(float* __restrict__ out) {
    const int t = blockIdx.x * RED_THREADS + threadIdx.x;  // 0..262143
    const int row = t >> 4;          // zb*128 + yb, 0..16383
    const int k0 = (t & 15) << 3;    // A x-brick base: 0,8,...,120

    uint4* A = reinterpret_cast<uint4*>(g_A) + (size_t)row * BRICKS + k0;
    uint4* B = reinterpret_cast<uint4*>(g_B) + (size_t)row * BX_B + k0;

    uint4 a[8], b[9];
#pragma unroll
    for (int k = 0; k < 8; k++) a[k] = A[k];
#pragma unroll
    for (int k = 0; k < 9; k++) b[k] = B[k];

    // Re-zero for the next graph replay. B brick 128 is zeroed by the
    // k0==120 thread (it loaded it); pad bricks 129..131 are never touched.
    const uint4 zero = make_uint4(0u, 0u, 0u, 0u);
#pragma unroll
    for (int k = 0; k < 8; k++) A[k] = zero;
#pragma unroll
    for (int k = 0; k < 8; k++) B[k] = zero;
    if (k0 == 120) B[8] = zero;

    float acc = 0.0f;
#pragma unroll
    for (int k = 0; k < 8; k++) {
        acc += pair_huber(a[k].x, b[k].x, b[k + 1].x);  // z0y0
        acc += pair_huber(a[k].y, b[k].y, b[k + 1].y);  // z0y1
        acc += pair_huber(a[k].z, b[k].z, b[k + 1].z);  // z1y0
        acc += pair_huber(a[k].w, b[k].w, b[k + 1].w);  // z1y1
    }

    // warp reduce
#pragma unroll
    for (int o = 16; o; o >>= 1) acc += __shfl_xor_sync(0xFFFFFFFFu, acc, o);

    __shared__ float sm[RED_THREADS / 32];
    int lane = threadIdx.x & 31;
    int wid = threadIdx.x >> 5;
    if (lane == 0) sm[wid] = acc;
    __syncthreads();
    if (wid == 0) {
        float vv = (lane < (RED_THREADS / 32)) ? sm[lane] : 0.0f;
#pragma unroll
        for (int o = 16; o; o >>= 1) vv += __shfl_xor_sync(0xFFFFFFFFu, vv, o);
        if (lane == 0) atomicAdd(out, vv);
    }
}

extern "C" void kernel_launch(void* const* d_in, const int* in_sizes, int n_in,
                              void* d_out, int out_size) {
    const float* pred   = (const float*)d_in[0];
    const float* gt     = (const float*)d_in[1];
    const float* coords = (const float*)d_in[2];
    float* out = (float*)d_out;

    int n = in_sizes[0] / 3;  // N_POINTS

    int threads = 256;
    int blocks = (n + threads - 1) / threads;
    scatter_kernel<<<blocks, threads>>>(pred, gt, coords, out, n);

    huber_reduce_kernel<<<RED_BLOCKS, RED_THREADS>>>(out);
}

// round 16
// speedup vs baseline: 1.2217x; 1.2217x over previous
#include <cuda_runtime.h>
#include <cuda_fp16.h>

#define GRID_SZ 256
#define BRICKS 128              // A-volume bricks per axis (2x2x2 cells)
#define BX_B   132              // B-volume x-brick stride (129 used, padded)

// Dual-grid fp16 difference volumes, 2x2x2-brick layout, 16 B per brick:
//   cell = (z&1)*4 + (y&1)*2 + (x&1)
// A: x-bricks aligned even: brick bx covers x in {2bx, 2bx+1},   bx in [0,127]
// B: x-bricks aligned odd:  brick j  covers x in {2j-1, 2j},     j  in [0,128]
// Even-x0 splats land wholly in one A x-brick; odd-x0 in one B x-brick ->
// exactly one RED per (y,z) brick combo: E[REDs/splat] = 1*1.5*1.5 = 2.25.
// Voxel value = A + B; the reduce gathers both (lane-interleaved, coalesced).
// Zero-initialized at load; the reduce re-zeros everything it reads.
__device__ __align__(16) __half g_A[(size_t)BRICKS * BRICKS * BRICKS * 8];
__device__ __align__(16) __half g_B[(size_t)BRICKS * BRICKS * BX_B * 8];

__device__ __forceinline__ void red_add_v4_h2(__half* addr, unsigned h0,
                                              unsigned h1, unsigned h2_,
                                              unsigned h3) {
    asm volatile("red.global.add.noftz.v4.f16x2 [%0], {%1,%2,%3,%4};"
                 :: "l"(addr), "r"(h0), "r"(h1), "r"(h2_), "r"(h3)
                 : "memory");
}

// y/z axes keep the 2-brick decomposition (shared alignment in A and B).
struct Axis {
    int n;
    int b[2];
    float w0[2], w1[2];
};

__device__ __forceinline__ Axis axis_decomp(int c0, float wlo, float whi) {
    Axis a;
    a.n = 0;
    int bA = c0 >> 1;  // arithmetic shift: c0=-1 -> -1 (rejected below)
    if (!(c0 & 1)) {
        if ((unsigned)bA < BRICKS) {
            a.b[0] = bA; a.w0[0] = wlo; a.w1[0] = whi; a.n = 1;
        }
    } else {
        if ((unsigned)bA < BRICKS) {
            a.b[a.n] = bA; a.w0[a.n] = 0.0f; a.w1[a.n] = wlo; a.n++;
        }
        int bB = bA + 1;
        if ((unsigned)bB < BRICKS) {
            a.b[a.n] = bB; a.w0[a.n] = whi; a.w1[a.n] = 0.0f; a.n++;
        }
    }
    return a;
}

__device__ __forceinline__ void splat(float px, float py, float pz, float s) {
    // Match reference arithmetic exactly: p = ((g+1)*size - 1) * 0.5
    float x = ((px + 1.0f) * 256.0f - 1.0f) * 0.5f;
    float y = ((py + 1.0f) * 256.0f - 1.0f) * 0.5f;
    float z = ((pz + 1.0f) * 256.0f - 1.0f) * 0.5f;
    float x0f = floorf(x), y0f = floorf(y), z0f = floorf(z);
    int x0 = (int)x0f, y0 = (int)y0f, z0 = (int)z0f;
    float fx = x - x0f, fy = y - y0f, fz = z - z0f;
    float wx0 = 1.0f - fx, wx1 = fx;

    // x-axis: single brick in A (x0 even) or B (x0 odd). Lane order (w0,w1)
    // is identical in both layouts.
    int par = x0 & 1;                 // works for negative x0 too
    int bx = (x0 >> 1) + par;         // even: x0>>1 ; odd: (x0+1)>>1
    __half* vol;
    int xstride;
    if (par) {
        if ((unsigned)bx > 128u) return;     // j in [0,128]
        if (x0 < 0) wx0 = 0.0f;              // lane x=-1 (exists, never read)
        if (x0 >= GRID_SZ - 1) wx1 = 0.0f;   // lane x=256
        vol = g_B; xstride = BX_B;
    } else {
        if ((unsigned)x0 >= (unsigned)(GRID_SZ - 1)) return; // x0 in [0,254]
        vol = g_A; xstride = BRICKS;
    }

    Axis ay = axis_decomp(y0, 1.0f - fy, fy);
    Axis az = axis_decomp(z0, (1.0f - fz) * s, fz * s);  // fold sign into z

#pragma unroll
    for (int i = 0; i < 2; i++) {
        if (i >= az.n) break;
        float t0 = az.w0[i], t1 = az.w1[i];
        int zb = az.b[i] * BRICKS;
#pragma unroll
        for (int j = 0; j < 2; j++) {
            if (j >= ay.n) break;
            float a00 = t0 * ay.w0[j];  // z0,y0
            float a01 = t0 * ay.w1[j];  // z0,y1
            float a10 = t1 * ay.w0[j];  // z1,y0
            float a11 = t1 * ay.w1[j];  // z1,y1
            __half* p = vol + ((size_t)(zb + ay.b[j]) * xstride + bx) * 8;
            __half2 q0 = __floats2half2_rn(a00 * wx0, a00 * wx1); // z0y0
            __half2 q1 = __floats2half2_rn(a01 * wx0, a01 * wx1); // z0y1
            __half2 q2 = __floats2half2_rn(a10 * wx0, a10 * wx1); // z1y0
            __half2 q3 = __floats2half2_rn(a11 * wx0, a11 * wx1); // z1y1
            red_add_v4_h2(p,
                          *(unsigned*)&q0, *(unsigned*)&q1,
                          *(unsigned*)&q2, *(unsigned*)&q3);
        }
    }
}

__global__ void scatter_kernel(const float* __restrict__ pred,
                               const float* __restrict__ gt,
                               const float* __restrict__ coords,
                               float* __restrict__ out, int n) {
    int i = blockIdx.x * blockDim.x + threadIdx.x;
    if (i == 0) out[0] = 0.0f;  // reduce kernel runs after us in stream order
    if (i >= n) return;

    // Streaming (evict-first) loads: keep L2 capacity for the volumes.
    float cx = __ldcs(&coords[3 * i + 0]);
    float cy = __ldcs(&coords[3 * i + 1]);
    float cz = __ldcs(&coords[3 * i + 2]);
    float p0 = __ldcs(&pred[3 * i + 0]);
    float p1 = __ldcs(&pred[3 * i + 1]);
    float p2 = __ldcs(&pred[3 * i + 2]);
    float g0 = __ldcs(&gt[3 * i + 0]);
    float g1 = __ldcs(&gt[3 * i + 1]);
    float g2 = __ldcs(&gt[3 * i + 2]);

    splat(cx + p0, cy + p1, cz + p2,  1.0f);
    splat(cx + g0, cy + g1, cz + g2, -1.0f);
}

__device__ __forceinline__ float huber(float d) {
    float ad = fabsf(d);
    return (ad <= 1.0f) ? 0.5f * d * d : (ad - 0.5f);
}

// A h2 (voxels x=2k lo, 2k+1 hi) + B[k] hi lane (x=2k) + B[k+1] lo (x=2k+1).
__device__ __forceinline__ float pair_huber(unsigned ua, unsigned ub0,
                                            unsigned ub1) {
    float2 fa = __half22float2(*(__half2*)&ua);
    float2 f0 = __half22float2(*(__half2*)&ub0);
    float2 f1 = __half22float2(*(__half2*)&ub1);
    return huber(fa.x + f0.y) + huber(fa.y + f1.x);
}

__device__ __forceinline__ uint4 shfl_down1_u4(uint4 v) {
    uint4 r;
    r.x = __shfl_down_sync(0xFFFFFFFFu, v.x, 1);
    r.y = __shfl_down_sync(0xFFFFFFFFu, v.y, 1);
    r.z = __shfl_down_sync(0xFFFFFFFFu, v.z, 1);
    r.w = __shfl_down_sync(0xFFFFFFFFu, v.w, 1);
    return r;
}

__device__ __forceinline__ uint4 shfl0_u4(uint4 v) {
    uint4 r;
    r.x = __shfl_sync(0xFFFFFFFFu, v.x, 0);
    r.y = __shfl_sync(0xFFFFFFFFu, v.y, 0);
    r.z = __shfl_sync(0xFFFFFFFFu, v.z, 0);
    r.w = __shfl_sync(0xFFFFFFFFu, v.w, 0);
    return r;
}

// One warp per 2 brick-rows (zb*128+yb). Lane l reads A_row[l+32k] (fully
// coalesced: 4 lines per warp-load) and B_row[l+32k]; the B[k+1] neighbor
// comes from shfl_down (lane 31 patched via shfl-from-0 / broadcast load of
// B_row[128]). 16384 rows / 2 = 8192 warps = 1024 blocks x 8 warps.
#define RED_BLOCKS 1024
#define RED_THREADS 256

__device__ __forceinline__ float row_reduce(uint4* Arow, uint4* Brow,
                                            int lane) {
    uint4 a[4], b[4];
#pragma unroll
    for (int k = 0; k < 4; k++) a[k] = Arow[lane + 32 * k];
#pragma unroll
    for (int k = 0; k < 4; k++) b[k] = Brow[lane + 32 * k];
    uint4 bend = Brow[128];  // broadcast load (all lanes same address)

    // Re-zero for the next graph replay.
    const uint4 zero = make_uint4(0u, 0u, 0u, 0u);
#pragma unroll
    for (int k = 0; k < 4; k++) Arow[lane + 32 * k] = zero;
#pragma unroll
    for (int k = 0; k < 4; k++) Brow[lane + 32 * k] = zero;
    if (lane == 31) Brow[128] = zero;

    float acc = 0.0f;
#pragma unroll
    for (int k = 0; k < 4; k++) {
        uint4 nb = shfl_down1_u4(b[k]);              // B[l+1+32k] for l<31
        uint4 fix = (k < 3) ? shfl0_u4(b[k + 1]) : bend;  // B[32k+32]
        if (lane == 31) nb = fix;
        acc += pair_huber(a[k].x, b[k].x, nb.x);  // z0y0
        acc += pair_huber(a[k].y, b[k].y, nb.y);  // z0y1
        acc += pair_huber(a[k].z, b[k].z, nb.z);  // z1y0
        acc += pair_huber(a[k].w, b[k].w, nb.w);  // z1y1
    }
    return acc;
}

__global__ void __launch_bounds__(RED_THREADS, 2)
huber_reduce_kernel(float* __restrict__ out) {
    const int wglob = (blockIdx.x * (RED_THREADS / 32)) + (threadIdx.x >> 5);
    const int lane = threadIdx.x & 31;
    const int row0 = wglob * 2;

    uint4* Abase = reinterpret_cast<uint4*>(g_A);
    uint4* Bbase = reinterpret_cast<uint4*>(g_B);

    float acc = row_reduce(Abase + (size_t)row0 * BRICKS,
                           Bbase + (size_t)row0 * BX_B, lane)
              + row_reduce(Abase + (size_t)(row0 + 1) * BRICKS,
                           Bbase + (size_t)(row0 + 1) * BX_B, lane);

    // warp reduce
#pragma unroll
    for (int o = 16; o; o >>= 1) acc += __shfl_xor_sync(0xFFFFFFFFu, acc, o);

    __shared__ float sm[RED_THREADS / 32];
    int wid = threadIdx.x >> 5;
    if (lane == 0) sm[wid] = acc;
    __syncthreads();
    if (wid == 0) {
        float vv = (lane < (RED_THREADS / 32)) ? sm[lane] : 0.0f;
#pragma unroll
        for (int o = 16; o; o >>= 1) vv += __shfl_xor_sync(0xFFFFFFFFu, vv, o);
        if (lane == 0) atomicAdd(out, vv);
    }
}

extern "C" void kernel_launch(void* const* d_in, const int* in_sizes, int n_in,
                              void* d_out, int out_size) {
    const float* pred   = (const float*)d_in[0];
    const float* gt     = (const float*)d_in[1];
    const float* coords = (const float*)d_in[2];
    float* out = (float*)d_out;

    int n = in_sizes[0] / 3;  // N_POINTS

    int threads = 256;
    int blocks = (n + threads - 1) / threads;
    scatter_kernel<<<blocks, threads>>>(pred, gt, coords, out, n);

    huber_reduce_kernel<<<RED_BLOCKS, RED_THREADS>>>(out);
}